// round 2
// baseline (speedup 1.0000x reference)
#include <cuda_runtime.h>
#include <math_constants.h>

#define BB 16
#define KK 256
#define ZZ 128
#define HH 128
#define BK (BB*KK)

typedef unsigned long long u64;
typedef unsigned int u32;

#define FMA2(d, a, b, c) \
  asm("fma.rn.f32x2 %0, %1, %2, %3;" : "=l"(d) : "l"(a), "l"(b), "l"(c))

__device__ __forceinline__ u64 pack2(float lo, float hi) {
  u64 r;
  asm("mov.b64 %0, {%1, %2};" : "=l"(r) : "f"(lo), "f"(hi));
  return r;
}
__device__ __forceinline__ float sum2(u64 p) {
  float lo, hi;
  asm("mov.b64 {%0, %1}, %2;" : "=f"(lo), "=f"(hi) : "l"(p));
  return lo + hi;
}

// scratch (allocation-free: __device__ globals)
__device__ float g_m1[BK*ZZ];
__device__ float g_m2[BK*ZZ];
__device__ float g_mm[BK*ZZ];

// ---------------------------------------------------------------------------
// Kernel 1: y = x @ W^T + b for both (W1,b1)->g_m1 and (W2,b2)->g_m2
// grid = (BK/16, 2), block = 256. Threads 0-127: rows 0-7, channel t.
// Threads 128-255: rows 8-15, channel t-128. Packed f32x2 FMAs.
// ---------------------------------------------------------------------------
__global__ __launch_bounds__(256) void lin_kernel(
    const float* __restrict__ z,
    const float* __restrict__ W1, const float* __restrict__ b1,
    const float* __restrict__ W2, const float* __restrict__ b2) {
  const float* W    = blockIdx.y ? W2 : W1;
  const float* bias = blockIdx.y ? b2 : b1;
  float*       y    = blockIdx.y ? g_m2 : g_m1;

  const int row0  = blockIdx.x * 16;
  const int tid   = threadIdx.x;
  const int t     = tid & 127;          // output channel
  const int rbase = (tid >> 7) * 8;     // row group 0..7 or 8..15

  __shared__ float xs[16][ZZ];
#pragma unroll
  for (int k = 0; k < 8; k++) {
    const int idx = k * 256 + tid;      // 0..2047
    xs[idx >> 7][idx & 127] = z[(row0 + (idx >> 7)) * ZZ + (idx & 127)];
  }
  __syncthreads();

  u64 acc[8];
#pragma unroll
  for (int r = 0; r < 8; r++) acc[r] = 0ULL;  // two zero floats

  const ulonglong2* Wr = (const ulonglong2*)(W + t * ZZ);
#pragma unroll 8
  for (int c4 = 0; c4 < ZZ / 4; c4++) {
    const ulonglong2 w = Wr[c4];
#pragma unroll
    for (int r = 0; r < 8; r++) {
      const ulonglong2 xv = *(const ulonglong2*)(&xs[rbase + r][c4 * 4]);
      FMA2(acc[r], w.x, xv.x, acc[r]);
      FMA2(acc[r], w.y, xv.y, acc[r]);
    }
  }

  const float bz = bias[t];
#pragma unroll
  for (int r = 0; r < 8; r++)
    y[(row0 + rbase + r) * ZZ + t] = sum2(acc[r]) + bz;
}

// ---------------------------------------------------------------------------
// Kernel 2: masked neighbor max + relu(m1 + max) -> g_mm
// grid = (K/16, B), block = 512 (warp = one destination node i)
// smem: dynamic 128KB m2z[b] tile + static 4KB adjacency byte table.
// ---------------------------------------------------------------------------
extern __shared__ float s_m2[];

__global__ __launch_bounds__(512) void maxagg_kernel(const int* __restrict__ P) {
  __shared__ unsigned char s_adj[KK * 16];  // [j][ii]

  const int b   = blockIdx.y;
  const int i0  = blockIdx.x * 16;
  const int tid = threadIdx.x;
  const int* Pb = P + b * KK * KK;

  // stage m2z[b] into smem (coalesced float4)
  {
    float4*       s4 = (float4*)s_m2;
    const float4* g4 = (const float4*)(g_m2 + b * KK * ZZ);
#pragma unroll
    for (int k = 0; k < KK * ZZ / 4 / 512; k++) s4[k * 512 + tid] = g4[k * 512 + tid];
  }
  // stage adjacency bytes, coalesced: s_adj[j*16+ii] = (P[b][j][i0+ii] != 0)
#pragma unroll
  for (int k = 0; k < 8; k++) {
    const int idx = k * 512 + tid;               // 0..4095
    const int j  = idx >> 4;
    const int ii = idx & 15;
    s_adj[idx] = (Pb[j * KK + i0 + ii] != 0);
  }
  __syncthreads();

  const int warp = tid >> 5;
  const int lane = tid & 31;
  const int i    = i0 + warp;

  // warp-uniform neighbor bitmasks from smem bytes
  unsigned words[8];
#pragma unroll
  for (int wd = 0; wd < 8; wd++) {
    const unsigned pv = s_adj[(wd * 32 + lane) * 16 + warp];
    words[wd] = __ballot_sync(0xFFFFFFFFu, pv != 0);
  }

  float4 acc = make_float4(-CUDART_INF_F, -CUDART_INF_F, -CUDART_INF_F, -CUDART_INF_F);
  const float4* sm = (const float4*)s_m2;  // [256][32] float4

#pragma unroll
  for (int wd = 0; wd < 8; wd++) {
    unsigned word = words[wd];
    const int base = wd * 32;
    while (word) {  // warp-uniform: only active neighbors
      const int j = base + __ffs((int)word) - 1;
      word &= word - 1;
      const float4 v = sm[j * (ZZ / 4) + lane];
      acc.x = fmaxf(acc.x, v.x);
      acc.y = fmaxf(acc.y, v.y);
      acc.z = fmaxf(acc.z, v.z);
      acc.w = fmaxf(acc.w, v.w);
    }
  }

  const int ri = (b * KK + i) * ZZ + lane * 4;
  const float4 m1 = *(const float4*)(g_m1 + ri);
  float4 o;
  o.x = fmaxf(m1.x + acc.x, 0.0f);
  o.y = fmaxf(m1.y + acc.y, 0.0f);
  o.z = fmaxf(m1.z + acc.z, 0.0f);
  o.w = fmaxf(m1.w + acc.w, 0.0f);
  *(float4*)(g_mm + ri) = o;
}

// ---------------------------------------------------------------------------
// Kernel 3: out = relu([z, m] @ Wu^T + bu), same structure as lin_kernel
// ---------------------------------------------------------------------------
__global__ __launch_bounds__(256) void out_kernel(
    const float* __restrict__ z,
    const float* __restrict__ Wu, const float* __restrict__ bu,
    float* __restrict__ out) {
  const int row0  = blockIdx.x * 16;
  const int tid   = threadIdx.x;
  const int t     = tid & 127;
  const int rbase = (tid >> 7) * 8;

  __shared__ float xs[16][2 * ZZ];
#pragma unroll
  for (int k = 0; k < 8; k++) {
    const int idx = k * 256 + tid;      // 0..2047 -> z half
    const int r = idx >> 7, c = idx & 127;
    xs[r][c]      = z[(row0 + r) * ZZ + c];
    xs[r][ZZ + c] = g_mm[(row0 + r) * ZZ + c];
  }
  __syncthreads();

  u64 acc[8];
#pragma unroll
  for (int r = 0; r < 8; r++) acc[r] = 0ULL;

  const ulonglong2* Wr = (const ulonglong2*)(Wu + t * 2 * ZZ);
#pragma unroll 8
  for (int c4 = 0; c4 < 2 * ZZ / 4; c4++) {
    const ulonglong2 w = Wr[c4];
#pragma unroll
    for (int r = 0; r < 8; r++) {
      const ulonglong2 xv = *(const ulonglong2*)(&xs[rbase + r][c4 * 4]);
      FMA2(acc[r], w.x, xv.x, acc[r]);
      FMA2(acc[r], w.y, xv.y, acc[r]);
    }
  }

  const float bz = bu[t];
#pragma unroll
  for (int r = 0; r < 8; r++)
    out[(row0 + rbase + r) * HH + t] = fmaxf(sum2(acc[r]) + bz, 0.0f);
}

// ---------------------------------------------------------------------------
extern "C" void kernel_launch(void* const* d_in, const int* in_sizes, int n_in,
                              void* d_out, int out_size) {
  const float* z  = (const float*)d_in[0];
  const int*   P  = (const int*)  d_in[1];
  const float* W1 = (const float*)d_in[2];
  const float* b1 = (const float*)d_in[3];
  const float* W2 = (const float*)d_in[4];
  const float* b2 = (const float*)d_in[5];
  const float* Wu = (const float*)d_in[6];
  const float* bu = (const float*)d_in[7];
  float* out = (float*)d_out;

  cudaFuncSetAttribute(maxagg_kernel, cudaFuncAttributeMaxDynamicSharedMemorySize,
                       KK * ZZ * (int)sizeof(float));

  lin_kernel<<<dim3(BK / 16, 2), 256>>>(z, W1, b1, W2, b2);
  maxagg_kernel<<<dim3(KK / 16, BB), 512, KK * ZZ * sizeof(float)>>>(P);
  out_kernel<<<BK / 16, 256>>>(z, Wu, bu, out);
}

// round 3
// speedup vs baseline: 1.0487x; 1.0487x over previous
#include <cuda_runtime.h>
#include <math_constants.h>

#define BB 16
#define KK 256
#define ZZ 128
#define HH 128
#define BK (BB*KK)

typedef unsigned long long u64;

#define FMA2(d, a, b, c) \
  asm("fma.rn.f32x2 %0, %1, %2, %3;" : "=l"(d) : "l"(a), "l"(b), "l"(c))

__device__ __forceinline__ u64 pack2(float lo, float hi) {
  u64 r;
  asm("mov.b64 %0, {%1, %2};" : "=l"(r) : "f"(lo), "f"(hi));
  return r;
}
__device__ __forceinline__ void unpack2(u64 p, float& lo, float& hi) {
  asm("mov.b64 {%0, %1}, %2;" : "=f"(lo), "=f"(hi) : "l"(p));
}

// scratch (allocation-free: __device__ globals)
__device__ float g_m1[BK*ZZ];
__device__ float g_m2[BK*ZZ];
__device__ float g_mm[BK*ZZ];
// packed transposed weights: WT2[k][cp] = {W[2cp][k], W[2cp+1][k]}
__device__ u64 g_wt1[ZZ * (ZZ/2)];        // [128][64]
__device__ u64 g_wt2[ZZ * (ZZ/2)];        // [128][64]
__device__ u64 g_wtu[(2*ZZ) * (HH/2)];    // [256][64]

// ---------------------------------------------------------------------------
// Pack kernel: build column-pair-packed transposed weights.
// 32768 u64 entries total. grid=128, block=256.
// ---------------------------------------------------------------------------
__global__ __launch_bounds__(256) void pack_kernel(
    const float* __restrict__ W1, const float* __restrict__ W2,
    const float* __restrict__ Wu) {
  const int idx = blockIdx.x * 256 + threadIdx.x;
  if (idx < 8192) {                       // W1: [128][128]
    const int k = idx & 127, cp = idx >> 7;
    g_wt1[k * 64 + cp] = pack2(W1[(2*cp)*ZZ + k], W1[(2*cp+1)*ZZ + k]);
  } else if (idx < 16384) {               // W2
    const int l = idx - 8192;
    const int k = l & 127, cp = l >> 7;
    g_wt2[k * 64 + cp] = pack2(W2[(2*cp)*ZZ + k], W2[(2*cp+1)*ZZ + k]);
  } else {                                // Wu: [128][256]
    const int l = idx - 16384;
    const int k = l & 255, cp = l >> 8;
    g_wtu[k * 64 + cp] = pack2(Wu[(2*cp)*(2*ZZ) + k], Wu[(2*cp+1)*(2*ZZ) + k]);
  }
}

// ---------------------------------------------------------------------------
// Kernel 1: y = x @ W^T + b for both weight sets.
// grid = (BK/32, 2), block = 128. Warp w owns rows w*8..w*8+7; lane owns
// cols lane*4..lane*4+3 (two packed col-pairs). Per k: 1 coalesced LDG.128
// of packed weights + 8 broadcast LDS.64 of splatted x + 16 FMA2.
// ---------------------------------------------------------------------------
__global__ __launch_bounds__(128) void lin_kernel(
    const float* __restrict__ z,
    const float* __restrict__ b1, const float* __restrict__ b2) {
  const u64*   WT   = blockIdx.y ? g_wt2 : g_wt1;
  const float* bias = blockIdx.y ? b2 : b1;
  float*       y    = blockIdx.y ? g_m2 : g_m1;

  __shared__ u64 xs[32][ZZ];   // splatted activations, 32KB
  const int tid  = threadIdx.x;
  const int lane = tid & 31;
  const int warp = tid >> 5;
  const int row0 = blockIdx.x * 32;

  // stage 32 rows of z as splat pairs (coalesced float4 reads)
  {
    const float4* zg = (const float4*)(z + row0 * ZZ);
#pragma unroll
    for (int c = 0; c < 8; c++) {
      const int idx = c * 128 + tid;       // float4 index 0..1023
      const float4 v = zg[idx];
      const int r = idx >> 5, k4 = (idx & 31) * 4;
      xs[r][k4+0] = pack2(v.x, v.x);
      xs[r][k4+1] = pack2(v.y, v.y);
      xs[r][k4+2] = pack2(v.z, v.z);
      xs[r][k4+3] = pack2(v.w, v.w);
    }
  }
  __syncthreads();

  u64 acc[8][2];
#pragma unroll
  for (int r = 0; r < 8; r++) { acc[r][0] = 0ULL; acc[r][1] = 0ULL; }

  const u64* xw = &xs[warp * 8][0];
  const ulonglong2* Wp = (const ulonglong2*)WT;

#pragma unroll 4
  for (int k = 0; k < ZZ; k++) {
    const ulonglong2 w = Wp[k * 32 + lane];
#pragma unroll
    for (int r = 0; r < 8; r++) {
      const u64 x = xw[r * ZZ + k];
      FMA2(acc[r][0], w.x, x, acc[r][0]);
      FMA2(acc[r][1], w.y, x, acc[r][1]);
    }
  }

  const float4 bv = ((const float4*)bias)[lane];
#pragma unroll
  for (int r = 0; r < 8; r++) {
    float a0, a1, a2, a3;
    unpack2(acc[r][0], a0, a1);
    unpack2(acc[r][1], a2, a3);
    const float4 o = make_float4(a0 + bv.x, a1 + bv.y, a2 + bv.z, a3 + bv.w);
    ((float4*)(y + (row0 + warp * 8 + r) * ZZ))[lane] = o;
  }
}

// ---------------------------------------------------------------------------
// Kernel 2: masked neighbor max + relu(m1 + max) -> g_mm
// grid = (K/32, B), block = 1024 (warp = one destination node i).
// smem: dynamic 128KB m2z[b] tile + static 8KB adjacency byte table.
// ---------------------------------------------------------------------------
extern __shared__ u64 dynsmem[];

__global__ __launch_bounds__(1024) void maxagg_kernel(const int* __restrict__ P) {
  __shared__ unsigned char s_adj[KK * 32];  // [j][ii], 8KB

  float* s_m2 = (float*)dynsmem;
  const int b   = blockIdx.y;
  const int i0  = blockIdx.x * 32;
  const int tid = threadIdx.x;
  const int* Pb = P + b * KK * KK;

  // stage m2z[b] (coalesced float4)
  {
    float4*       s4 = (float4*)s_m2;
    const float4* g4 = (const float4*)(g_m2 + b * KK * ZZ);
#pragma unroll
    for (int c = 0; c < KK * ZZ / 4 / 1024; c++) s4[c * 1024 + tid] = g4[c * 1024 + tid];
  }
  // stage adjacency bytes coalesced: s_adj[j*32+ii] = (P[b][j][i0+ii] != 0)
#pragma unroll
  for (int c = 0; c < 8; c++) {
    const int idx = c * 1024 + tid;              // 0..8191
    const int j  = idx >> 5;
    const int ii = idx & 31;
    s_adj[idx] = (Pb[j * KK + i0 + ii] != 0);
  }
  __syncthreads();

  const int warp = tid >> 5;
  const int lane = tid & 31;
  const int i    = i0 + warp;

  unsigned words[8];
#pragma unroll
  for (int wd = 0; wd < 8; wd++) {
    const unsigned pv = s_adj[(wd * 32 + lane) * 32 + warp];
    words[wd] = __ballot_sync(0xFFFFFFFFu, pv != 0);
  }

  float4 acc = make_float4(-CUDART_INF_F, -CUDART_INF_F, -CUDART_INF_F, -CUDART_INF_F);
  const float4* sm = (const float4*)s_m2;  // [256][32] float4

#pragma unroll
  for (int wd = 0; wd < 8; wd++) {
    unsigned word = words[wd];
    const int base = wd * 32;
    while (word) {  // warp-uniform: only active neighbors
      const int j = base + __ffs((int)word) - 1;
      word &= word - 1;
      const float4 v = sm[j * (ZZ / 4) + lane];
      acc.x = fmaxf(acc.x, v.x);
      acc.y = fmaxf(acc.y, v.y);
      acc.z = fmaxf(acc.z, v.z);
      acc.w = fmaxf(acc.w, v.w);
    }
  }

  const int ri = (b * KK + i) * ZZ + lane * 4;
  const float4 m1 = *(const float4*)(g_m1 + ri);
  float4 o;
  o.x = fmaxf(m1.x + acc.x, 0.0f);
  o.y = fmaxf(m1.y + acc.y, 0.0f);
  o.z = fmaxf(m1.z + acc.z, 0.0f);
  o.w = fmaxf(m1.w + acc.w, 0.0f);
  *(float4*)(g_mm + ri) = o;
}

// ---------------------------------------------------------------------------
// Kernel 3: out = relu([z, m] @ Wu^T + bu). Same tiling as lin, K=256.
// smem: dynamic 64KB (splatted [z | m] tile).
// ---------------------------------------------------------------------------
__global__ __launch_bounds__(128) void out_kernel(
    const float* __restrict__ z,
    const float* __restrict__ bu, float* __restrict__ out) {
  u64 (*xs)[2*ZZ] = (u64(*)[2*ZZ])dynsmem;   // [32][256] u64 = 64KB

  const int tid  = threadIdx.x;
  const int lane = tid & 31;
  const int warp = tid >> 5;
  const int row0 = blockIdx.x * 32;

  {
    const float4* zg = (const float4*)(z + row0 * ZZ);
    const float4* mg = (const float4*)(g_mm + row0 * ZZ);
#pragma unroll
    for (int c = 0; c < 8; c++) {
      const int idx = c * 128 + tid;
      const int r = idx >> 5, k4 = (idx & 31) * 4;
      const float4 v = zg[idx];
      xs[r][k4+0] = pack2(v.x, v.x);
      xs[r][k4+1] = pack2(v.y, v.y);
      xs[r][k4+2] = pack2(v.z, v.z);
      xs[r][k4+3] = pack2(v.w, v.w);
      const float4 m = mg[idx];
      xs[r][ZZ+k4+0] = pack2(m.x, m.x);
      xs[r][ZZ+k4+1] = pack2(m.y, m.y);
      xs[r][ZZ+k4+2] = pack2(m.z, m.z);
      xs[r][ZZ+k4+3] = pack2(m.w, m.w);
    }
  }
  __syncthreads();

  u64 acc[8][2];
#pragma unroll
  for (int r = 0; r < 8; r++) { acc[r][0] = 0ULL; acc[r][1] = 0ULL; }

  const u64* xw = &xs[warp * 8][0];
  const ulonglong2* Wp = (const ulonglong2*)g_wtu;

#pragma unroll 4
  for (int k = 0; k < 2*ZZ; k++) {
    const ulonglong2 w = Wp[k * 32 + lane];
#pragma unroll
    for (int r = 0; r < 8; r++) {
      const u64 x = xw[r * (2*ZZ) + k];
      FMA2(acc[r][0], w.x, x, acc[r][0]);
      FMA2(acc[r][1], w.y, x, acc[r][1]);
    }
  }

  const float4 bv = ((const float4*)bu)[lane];
#pragma unroll
  for (int r = 0; r < 8; r++) {
    float a0, a1, a2, a3;
    unpack2(acc[r][0], a0, a1);
    unpack2(acc[r][1], a2, a3);
    float4 o;
    o.x = fmaxf(a0 + bv.x, 0.0f);
    o.y = fmaxf(a1 + bv.y, 0.0f);
    o.z = fmaxf(a2 + bv.z, 0.0f);
    o.w = fmaxf(a3 + bv.w, 0.0f);
    ((float4*)(out + (row0 + warp * 8 + r) * HH))[lane] = o;
  }
}

// ---------------------------------------------------------------------------
extern "C" void kernel_launch(void* const* d_in, const int* in_sizes, int n_in,
                              void* d_out, int out_size) {
  const float* z  = (const float*)d_in[0];
  const int*   P  = (const int*)  d_in[1];
  const float* W1 = (const float*)d_in[2];
  const float* b1 = (const float*)d_in[3];
  const float* W2 = (const float*)d_in[4];
  const float* b2 = (const float*)d_in[5];
  const float* Wu = (const float*)d_in[6];
  const float* bu = (const float*)d_in[7];
  float* out = (float*)d_out;

  cudaFuncSetAttribute(maxagg_kernel, cudaFuncAttributeMaxDynamicSharedMemorySize,
                       KK * ZZ * (int)sizeof(float));
  cudaFuncSetAttribute(out_kernel, cudaFuncAttributeMaxDynamicSharedMemorySize,
                       32 * 2 * ZZ * (int)sizeof(u64));

  pack_kernel<<<128, 256>>>(W1, W2, Wu);
  lin_kernel<<<dim3(BK / 32, 2), 128>>>(z, b1, b2);
  maxagg_kernel<<<dim3(KK / 32, BB), 1024, KK * ZZ * sizeof(float)>>>(P);
  out_kernel<<<BK / 32, 128, 32 * 2 * ZZ * sizeof(u64)>>>(z, bu, out);
}

// round 5
// speedup vs baseline: 1.5697x; 1.4968x over previous
#include <cuda_runtime.h>
#include <math_constants.h>

#define BB 16
#define KK 256
#define ZZ 128
#define HH 128
#define BK (BB*KK)

typedef unsigned long long u64;

#define FMA2(d, a, b, c) \
  asm("fma.rn.f32x2 %0, %1, %2, %3;" : "=l"(d) : "l"(a), "l"(b), "l"(c))

__device__ __forceinline__ u64 pack2(float lo, float hi) {
  u64 r;
  asm("mov.b64 %0, {%1, %2};" : "=l"(r) : "f"(lo), "f"(hi));
  return r;
}
__device__ __forceinline__ void unpack2(u64 p, float& lo, float& hi) {
  asm("mov.b64 {%0, %1}, %2;" : "=f"(lo), "=f"(hi) : "l"(p));
}

// scratch (allocation-free: __device__ globals)
__device__ float g_m1[BK*ZZ];
__device__ float g_m2[BK*ZZ];
__device__ float g_mm[BK*ZZ];
// packed transposed weights: WT2[k][cp] = {W[2cp][k], W[2cp+1][k]}
__device__ u64 g_wt1[ZZ * (ZZ/2)];        // [128][64]
__device__ u64 g_wt2[ZZ * (ZZ/2)];        // [128][64]
__device__ u64 g_wtu[(2*ZZ) * (HH/2)];    // [256][64]

extern __shared__ u64 dynsmem[];

// ---------------------------------------------------------------------------
// Pack kernel: column-pair-packed transposed weights. grid=128, block=256.
// ---------------------------------------------------------------------------
__global__ __launch_bounds__(256) void pack_kernel(
    const float* __restrict__ W1, const float* __restrict__ W2,
    const float* __restrict__ Wu) {
  const int idx = blockIdx.x * 256 + threadIdx.x;
  if (idx < 8192) {
    const int k = idx & 127, cp = idx >> 7;
    g_wt1[k * 64 + cp] = pack2(W1[(2*cp)*ZZ + k], W1[(2*cp+1)*ZZ + k]);
  } else if (idx < 16384) {
    const int l = idx - 8192;
    const int k = l & 127, cp = l >> 7;
    g_wt2[k * 64 + cp] = pack2(W2[(2*cp)*ZZ + k], W2[(2*cp+1)*ZZ + k]);
  } else {
    const int l = idx - 16384;
    const int k = l & 255, cp = l >> 8;
    g_wtu[k * 64 + cp] = pack2(Wu[(2*cp)*(2*ZZ) + k], Wu[(2*cp+1)*(2*ZZ) + k]);
  }
}

// ---------------------------------------------------------------------------
// Kernel 1: y = x @ W^T + b for both weight sets. grid=(64,2), block=256.
// smem: sw[128k][64cp] u64 (64KB) + sx[64row][128k] splat u64 (64KB).
// Warp owns 8 rows; lane owns 4 cols (2 colpairs). Pure-smem inner loop.
// ---------------------------------------------------------------------------
__global__ __launch_bounds__(256) void lin_kernel(
    const float* __restrict__ z,
    const float* __restrict__ b1, const float* __restrict__ b2) {
  const u64*   WT   = blockIdx.y ? g_wt2 : g_wt1;
  const float* bias = blockIdx.y ? b2 : b1;
  float*       y    = blockIdx.y ? g_m2 : g_m1;

  u64* sw = dynsmem;               // [128][64]
  u64* sx = dynsmem + 128 * 64;    // [64][128]

  const int tid  = threadIdx.x;
  const int row0 = blockIdx.x * 64;

  // stage packed weights (straight 64KB copy, coalesced 16B)
  {
    ulonglong2*       d = (ulonglong2*)sw;
    const ulonglong2* s = (const ulonglong2*)WT;
#pragma unroll
    for (int i = 0; i < 16; i++) d[i * 256 + tid] = s[i * 256 + tid];
  }
  // stage splatted activations
  {
    const float4* zg = (const float4*)(z + row0 * ZZ);  // 2048 float4
#pragma unroll
    for (int i = 0; i < 8; i++) {
      const int idx = i * 256 + tid;
      const float4 v = zg[idx];
      u64* p = sx + (idx >> 5) * ZZ + (idx & 31) * 4;
      p[0] = pack2(v.x, v.x); p[1] = pack2(v.y, v.y);
      p[2] = pack2(v.z, v.z); p[3] = pack2(v.w, v.w);
    }
  }
  __syncthreads();

  const int lane = tid & 31;
  const int warp = tid >> 5;
  const u64* xb = sx + warp * 8 * ZZ;

  u64 acc[8][2];
#pragma unroll
  for (int r = 0; r < 8; r++) { acc[r][0] = 0ULL; acc[r][1] = 0ULL; }

#pragma unroll 4
  for (int k = 0; k < ZZ; k += 2) {
    const ulonglong2 wa = *(const ulonglong2*)(sw + k * 64 + lane * 2);
    const ulonglong2 wb = *(const ulonglong2*)(sw + (k + 1) * 64 + lane * 2);
#pragma unroll
    for (int r = 0; r < 8; r++) {
      const ulonglong2 xp = *(const ulonglong2*)(xb + r * ZZ + k);  // {x_k,x_k} {x_k1,x_k1}
      FMA2(acc[r][0], wa.x, xp.x, acc[r][0]);
      FMA2(acc[r][1], wa.y, xp.x, acc[r][1]);
      FMA2(acc[r][0], wb.x, xp.y, acc[r][0]);
      FMA2(acc[r][1], wb.y, xp.y, acc[r][1]);
    }
  }

  const float4 bv = ((const float4*)bias)[lane];
#pragma unroll
  for (int r = 0; r < 8; r++) {
    float a0, a1, a2, a3;
    unpack2(acc[r][0], a0, a1);
    unpack2(acc[r][1], a2, a3);
    const float4 o = make_float4(a0 + bv.x, a1 + bv.y, a2 + bv.z, a3 + bv.w);
    ((float4*)(y + (row0 + warp * 8 + r) * ZZ))[lane] = o;
  }
}

// ---------------------------------------------------------------------------
// Kernel 2: masked neighbor max + relu(m1 + max) -> g_mm
// grid = (K/32, B), block = 1024 (warp = destination node i).
// ---------------------------------------------------------------------------
__global__ __launch_bounds__(1024) void maxagg_kernel(const int* __restrict__ P) {
  __shared__ unsigned char s_adj[KK * 32];  // 8KB

  float* s_m2 = (float*)dynsmem;
  const int b   = blockIdx.y;
  const int i0  = blockIdx.x * 32;
  const int tid = threadIdx.x;
  const int* Pb = P + b * KK * KK;

  {
    float4*       s4 = (float4*)s_m2;
    const float4* g4 = (const float4*)(g_m2 + b * KK * ZZ);
#pragma unroll
    for (int c = 0; c < KK * ZZ / 4 / 1024; c++) s4[c * 1024 + tid] = g4[c * 1024 + tid];
  }
#pragma unroll
  for (int c = 0; c < 8; c++) {
    const int idx = c * 1024 + tid;
    s_adj[idx] = (Pb[(idx >> 5) * KK + i0 + (idx & 31)] != 0);
  }
  __syncthreads();

  const int warp = tid >> 5;
  const int lane = tid & 31;
  const int i    = i0 + warp;

  unsigned words[8];
#pragma unroll
  for (int wd = 0; wd < 8; wd++) {
    const unsigned pv = s_adj[(wd * 32 + lane) * 32 + warp];
    words[wd] = __ballot_sync(0xFFFFFFFFu, pv != 0);
  }

  float4 acc = make_float4(-CUDART_INF_F, -CUDART_INF_F, -CUDART_INF_F, -CUDART_INF_F);
  const float4* sm = (const float4*)s_m2;

#pragma unroll
  for (int wd = 0; wd < 8; wd++) {
    unsigned word = words[wd];
    const int base = wd * 32;
    while (word) {
      const int j = base + __ffs((int)word) - 1;
      word &= word - 1;
      const float4 v = sm[j * (ZZ / 4) + lane];
      acc.x = fmaxf(acc.x, v.x);
      acc.y = fmaxf(acc.y, v.y);
      acc.z = fmaxf(acc.z, v.z);
      acc.w = fmaxf(acc.w, v.w);
    }
  }

  const int ri = (b * KK + i) * ZZ + lane * 4;
  const float4 m1 = *(const float4*)(g_m1 + ri);
  float4 o;
  o.x = fmaxf(m1.x + acc.x, 0.0f);
  o.y = fmaxf(m1.y + acc.y, 0.0f);
  o.z = fmaxf(m1.z + acc.z, 0.0f);
  o.w = fmaxf(m1.w + acc.w, 0.0f);
  *(float4*)(g_mm + ri) = o;
}

// ---------------------------------------------------------------------------
// Kernel 3: out = relu([z, m] @ Wu^T + bu). grid=(64 rowblk, 2 colhalf), 256 thr.
// smem: sw k-pair interleaved (64KB) + sx[64][256] splat (128KB) = 192KB.
// Warp owns 8 rows; lane owns 1 colpair (2 cols) of its 64-col half.
// ---------------------------------------------------------------------------
__global__ __launch_bounds__(256) void out_kernel(
    const float* __restrict__ z,
    const float* __restrict__ bu, float* __restrict__ out) {
  u64* sw = dynsmem;               // u64 at (k>>1)*64 + cpl*2 + (k&1)
  u64* sx = dynsmem + 8192;        // [64][256]

  const int tid  = threadIdx.x;
  const int h    = blockIdx.y;       // column half
  const int row0 = blockIdx.x * 64;

  // stage weight half, k-pair interleaved
#pragma unroll 2
  for (int c = 0; c < 32; c++) {
    const int idx = c * 256 + tid;          // 0..8191
    const int k = idx >> 5, cpl = idx & 31;
    sw[(k >> 1) * 64 + cpl * 2 + (k & 1)] = g_wtu[k * 64 + h * 32 + cpl];
  }
  // stage splatted [z | m] tile
  {
    const float4* zg = (const float4*)(z + row0 * ZZ);
    const float4* mg = (const float4*)(g_mm + row0 * ZZ);
#pragma unroll 2
    for (int c = 0; c < 8; c++) {
      const int idx = c * 256 + tid;
      const int r = idx >> 5, k4 = (idx & 31) * 4;
      const float4 v = zg[idx];
      u64* p = sx + r * 256 + k4;
      p[0] = pack2(v.x, v.x); p[1] = pack2(v.y, v.y);
      p[2] = pack2(v.z, v.z); p[3] = pack2(v.w, v.w);
      const float4 m = mg[idx];
      u64* q = p + ZZ;
      q[0] = pack2(m.x, m.x); q[1] = pack2(m.y, m.y);
      q[2] = pack2(m.z, m.z); q[3] = pack2(m.w, m.w);
    }
  }
  __syncthreads();

  const int lane = tid & 31;
  const int warp = tid >> 5;
  const u64* xb = sx + warp * 8 * 256;

  u64 acc[8];
#pragma unroll
  for (int r = 0; r < 8; r++) acc[r] = 0ULL;

#pragma unroll 4
  for (int kk = 0; kk < 128; kk++) {   // two k per iter
    const ulonglong2 w2 = *(const ulonglong2*)(sw + kk * 64 + lane * 2);
#pragma unroll
    for (int r = 0; r < 8; r++) {
      const ulonglong2 xp = *(const ulonglong2*)(xb + r * 256 + kk * 2);
      FMA2(acc[r], w2.x, xp.x, acc[r]);
      FMA2(acc[r], w2.y, xp.y, acc[r]);
    }
  }

  const float2 bv = ((const float2*)bu)[h * 32 + lane];
#pragma unroll
  for (int r = 0; r < 8; r++) {
    float a0, a1;
    unpack2(acc[r], a0, a1);
    float2 o;
    o.x = fmaxf(a0 + bv.x, 0.0f);
    o.y = fmaxf(a1 + bv.y, 0.0f);
    ((float2*)(out + (row0 + warp * 8 + r) * HH + h * 64))[lane] = o;
  }
}

// ---------------------------------------------------------------------------
extern "C" void kernel_launch(void* const* d_in, const int* in_sizes, int n_in,
                              void* d_out, int out_size) {
  const float* z  = (const float*)d_in[0];
  const int*   P  = (const int*)  d_in[1];
  const float* W1 = (const float*)d_in[2];
  const float* b1 = (const float*)d_in[3];
  const float* W2 = (const float*)d_in[4];
  const float* b2 = (const float*)d_in[5];
  const float* Wu = (const float*)d_in[6];
  const float* bu = (const float*)d_in[7];
  float* out = (float*)d_out;

  (void)cudaFuncSetAttribute(lin_kernel, cudaFuncAttributeMaxDynamicSharedMemorySize, 131072);
  (void)cudaFuncSetAttribute(maxagg_kernel, cudaFuncAttributeMaxDynamicSharedMemorySize, 131072);
  (void)cudaFuncSetAttribute(out_kernel, cudaFuncAttributeMaxDynamicSharedMemorySize, 196608);

  pack_kernel<<<128, 256>>>(W1, W2, Wu);
  lin_kernel<<<dim3(64, 2), 256, 131072>>>(z, b1, b2);
  maxagg_kernel<<<dim3(KK / 32, BB), 1024, KK * ZZ * sizeof(float)>>>(P);
  out_kernel<<<dim3(64, 2), 256, 196608>>>(z, bu, out);
}